// round 7
// baseline (speedup 1.0000x reference)
#include <cuda_runtime.h>
#include <cuda_bf16.h>
#include <cstdint>

// ---------------------------------------------------------------------------
// GAT layer: B=4, N=4096, F_in=F_out=128
// K1: Wh (fp32) -> V (tf32), si, sj   (si,sj pre-scaled by log2(e))
// K2: fused masked-softmax + PV via mma.sync tf32
//     - P computed directly in A-fragment layout (STS.128 / LDS.128)
//     - one barrier per tile, PF double-buffered, cp.async V double-buffered
//     - adj/sj register prefetch hidden under MMA
// ---------------------------------------------------------------------------

#define NB   4
#define NN   4096
#define NF   128
#define BM   64
#define BN   64

__device__ float g_V[(size_t)NB * NN * NF];
__device__ float g_si[NB * NN];     // scaled by LOG2E
__device__ float g_sj[NB * NN];     // scaled by LOG2E

#define LOG2E 1.4426950408889634f

__device__ __forceinline__ float to_tf32(float x) {
    float y;
    asm("cvt.rna.tf32.f32 %0, %1;" : "=f"(y) : "f"(x));
    return y;
}

// ---------------------------------------------------------------------------
// Kernel 1: Wh = h @ W, si, sj. 16 rows per block, 128 threads.
// ---------------------------------------------------------------------------
#define K1R 16
__global__ __launch_bounds__(128) void gat_k1(const float* __restrict__ h,
                                              const float* __restrict__ W,
                                              const float* __restrict__ a) {
    __shared__ float hs[K1R][128];
    __shared__ float red[2][K1R][4];
    const int tid = threadIdx.x;
    const int base = blockIdx.x * K1R;

#pragma unroll
    for (int r = 0; r < K1R; r++)
        hs[r][tid] = h[(size_t)(base + r) * NF + tid];
    __syncthreads();

    float acc[K1R];
#pragma unroll
    for (int r = 0; r < K1R; r++) acc[r] = 0.f;

#pragma unroll 4
    for (int f = 0; f < NF; f++) {
        const float w = W[f * NF + tid];
#pragma unroll
        for (int r = 0; r < K1R; r++)
            acc[r] = fmaf(hs[r][f], w, acc[r]);
    }

    const float ai = a[tid] * LOG2E;
    const float aj = a[NF + tid] * LOG2E;
    const int lane = tid & 31, warp = tid >> 5;

#pragma unroll
    for (int r = 0; r < K1R; r++) {
        g_V[(size_t)(base + r) * NF + tid] = to_tf32(acc[r]);
        float pi = acc[r] * ai;
        float pj = acc[r] * aj;
#pragma unroll
        for (int off = 16; off > 0; off >>= 1) {
            pi += __shfl_xor_sync(0xffffffffu, pi, off);
            pj += __shfl_xor_sync(0xffffffffu, pj, off);
        }
        if (lane == 0) { red[0][r][warp] = pi; red[1][r][warp] = pj; }
    }
    __syncthreads();
    if (tid < 32) {
        const int r = tid & 15, which = tid >> 4;
        const float s = red[which][r][0] + red[which][r][1] +
                        red[which][r][2] + red[which][r][3];
        (which ? g_sj : g_si)[base + r] = s;
    }
}

// ---------------------------------------------------------------------------
// Kernel 2
// smem: PF[2][4096] (P in fragment layout), Vs[2][64*136], rsum[64]
// PF float4 index: ((ms*8 + k8)*32 + lane)  where lane = ar*4+ac
//   float4 = { P[16ms+ar][8k8+ac], P[16ms+ar+8][8k8+ac],
//              P[16ms+ar][8k8+ac+4], P[16ms+ar+8][8k8+ac+4] }
// ---------------------------------------------------------------------------
#define VS_STRIDE 136
#define PF_FLOATS 4096
#define VS_FLOATS (BN * VS_STRIDE)
#define SMEM_FLOATS (2 * PF_FLOATS + 2 * VS_FLOATS + 64)

#define CP_ASYNC16(dst_u32, src_ptr) \
    asm volatile("cp.async.cg.shared.global [%0], [%1], 16;" \
                 :: "r"(dst_u32), "l"(src_ptr))
#define CP_COMMIT()  asm volatile("cp.async.commit_group;" ::: "memory")
#define CP_WAIT1()   asm volatile("cp.async.wait_group 1;"  ::: "memory")

__device__ __forceinline__ float pval(float si, float sj, int m) {
    float t = si + sj;
    t = t > 0.f ? t : 0.2f * t;
    float e;
    asm("ex2.approx.f32 %0, %1;" : "=f"(e) : "f"(t));
    return m ? e : 0.f;
}

__global__ __launch_bounds__(256, 2) void gat_k2(const int* __restrict__ adj,
                                                 float* __restrict__ out) {
    extern __shared__ float smem[];
    float* PF   = smem;                         // 2 x 4096
    float* Vs   = smem + 2 * PF_FLOATS;         // 2 x 64*136
    float* rsum = Vs + 2 * VS_FLOATS;           // 64

    const int tid  = threadIdx.x;
    const int lane = tid & 31, warp = tid >> 5;
    const int b  = blockIdx.x >> 6;
    const int i0 = (blockIdx.x & 63) * BM;

    // fragment mapping (shared by P-phase and MMA-phase)
    const int k8 = warp;                 // P-phase k-chunk owned by this warp
    const int ar = lane >> 2;
    const int ac = lane & 3;
    const int c0 = k8 * 8 + ac;          // P-phase col (other col = c0+4)

    const int*   adj_b = adj + ((size_t)(b * NN + i0)) * NN;
    const float* sjb   = g_sj + b * NN;
    const float* Vg    = g_V + (size_t)b * NN * NF;

    // si for this thread's 8 rows (tile-invariant): rows 16*ms + ar + 8*rh
    float sie[8];
#pragma unroll
    for (int ms = 0; ms < 4; ms++) {
        sie[ms * 2 + 0] = g_si[b * NN + i0 + 16 * ms + ar];
        sie[ms * 2 + 1] = g_si[b * NN + i0 + 16 * ms + ar + 8];
    }

    // MMA warp tiling: m32 x n32
    const int wm = (warp & 1) * 32;
    const int wn = (warp >> 1) * 32;
    const int ms0 = (warp & 1) * 2;

    // V staging
    const int vr0 = tid >> 5;
    const int vc4 = (tid & 31) << 2;
    const uint32_t vs_base = (uint32_t)__cvta_generic_to_shared(Vs);

    float acc[2][4][4];
#pragma unroll
    for (int mt = 0; mt < 2; mt++)
#pragma unroll
        for (int nt = 0; nt < 4; nt++)
#pragma unroll
            for (int j = 0; j < 4; j++) acc[mt][nt][j] = 0.f;
    float rs[8];
#pragma unroll
    for (int r = 0; r < 8; r++) rs[r] = 0.f;

    // ---- prologue: V(0) via cp.async (buf 0), adj(0)/sj(0) into regs ----
#pragma unroll
    for (int q = 0; q < 8; q++) {
        const int vr = vr0 + q * 8;
        CP_ASYNC16(vs_base + (uint32_t)((vr * VS_STRIDE + vc4) * 4),
                   Vg + (size_t)vr * NF + vc4);
    }
    CP_COMMIT();

    int adv[16];
    float sj0, sj1;
#pragma unroll
    for (int r8 = 0; r8 < 8; r8++) {
        const int row = 16 * (r8 >> 1) + ar + 8 * (r8 & 1);
        adv[r8 * 2 + 0] = adj_b[(size_t)row * NN + c0];
        adv[r8 * 2 + 1] = adj_b[(size_t)row * NN + c0 + 4];
    }
    sj0 = sjb[c0];
    sj1 = sjb[c0 + 4];

    for (int jt = 0; jt < NN / BN; jt++) {
        const int buf = jt & 1;

        // ---- P-phase: fragment-native, one STS.128 per ms ----
        float* pf = PF + buf * PF_FLOATS;
#pragma unroll
        for (int ms = 0; ms < 4; ms++) {
            const float p00 = pval(sie[ms * 2 + 0], sj0, adv[(ms * 2 + 0) * 2 + 0]);
            const float p10 = pval(sie[ms * 2 + 1], sj0, adv[(ms * 2 + 1) * 2 + 0]);
            const float p01 = pval(sie[ms * 2 + 0], sj1, adv[(ms * 2 + 0) * 2 + 1]);
            const float p11 = pval(sie[ms * 2 + 1], sj1, adv[(ms * 2 + 1) * 2 + 1]);
            rs[ms * 2 + 0] += p00 + p01;
            rs[ms * 2 + 1] += p10 + p11;
            float4 v; v.x = p00; v.y = p10; v.z = p01; v.w = p11;
            *(float4*)(pf + ((ms * 8 + k8) * 32 + lane) * 4) = v;
        }

        __syncthreads();   // PF[buf] visible; all MMA(jt-1) reads complete

        // ---- prefetch tile jt+1 (after barrier: no race vs MMA(jt-1)) ----
        if (jt + 1 < NN / BN) {
            const int j1 = (jt + 1) * BN;
            const uint32_t vb = vs_base +
                                (uint32_t)((buf ^ 1) * VS_FLOATS * 4);
#pragma unroll
            for (int q = 0; q < 8; q++) {
                const int vr = vr0 + q * 8;
                CP_ASYNC16(vb + (uint32_t)((vr * VS_STRIDE + vc4) * 4),
                           Vg + (size_t)(j1 + vr) * NF + vc4);
            }
            CP_COMMIT();
#pragma unroll
            for (int r8 = 0; r8 < 8; r8++) {
                const int row = 16 * (r8 >> 1) + ar + 8 * (r8 & 1);
                adv[r8 * 2 + 0] = adj_b[(size_t)row * NN + j1 + c0];
                adv[r8 * 2 + 1] = adj_b[(size_t)row * NN + j1 + c0 + 4];
            }
            sj0 = sjb[j1 + c0];
            sj1 = sjb[j1 + c0 + 4];
        } else {
            CP_COMMIT();
        }
        CP_WAIT1();        // V(jt) landed; V(jt+1) still in flight

        // ---- MMA: acc += P(64x64) @ V(64x128) ----
        const float*    pfr = PF + buf * PF_FLOATS;
        const uint32_t* Vsu = (const uint32_t*)(Vs + buf * VS_FLOATS);
#pragma unroll
        for (int kk = 0; kk < 8; kk++) {
            uint4 af[2];
#pragma unroll
            for (int mt = 0; mt < 2; mt++)
                af[mt] = *(const uint4*)(pfr + (((ms0 + mt) * 8 + kk) * 32 + lane) * 4);
#pragma unroll
            for (int nt = 0; nt < 4; nt++) {
                const int n0 = wn + nt * 8;
                const uint32_t b0 = Vsu[(kk * 8 + ac)     * VS_STRIDE + n0 + ar];
                const uint32_t b1 = Vsu[(kk * 8 + ac + 4) * VS_STRIDE + n0 + ar];
#pragma unroll
                for (int mt = 0; mt < 2; mt++) {
                    asm volatile(
                        "mma.sync.aligned.m16n8k8.row.col.f32.tf32.tf32.f32 "
                        "{%0,%1,%2,%3}, {%4,%5,%6,%7}, {%8,%9}, {%0,%1,%2,%3};\n"
                        : "+f"(acc[mt][nt][0]), "+f"(acc[mt][nt][1]),
                          "+f"(acc[mt][nt][2]), "+f"(acc[mt][nt][3])
                        : "r"(af[mt].x), "r"(af[mt].y),
                          "r"(af[mt].z), "r"(af[mt].w),
                          "r"(b0), "r"(b1));
                }
            }
        }
    }

    // ---- row-sum reduction (reuse PF as Red[64][33]) ----
    __syncthreads();
    float* Red = PF;
#pragma unroll
    for (int r8 = 0; r8 < 8; r8++) {
        const int row = 16 * (r8 >> 1) + ar + 8 * (r8 & 1);
        Red[row * 33 + k8 * 4 + ac] = rs[r8];
    }
    __syncthreads();
    if (tid < 64) {
        float s = 0.f;
#pragma unroll
        for (int k = 0; k < 32; k++) s += Red[tid * 33 + k];
        rsum[tid] = s;
    }
    __syncthreads();

    // ---- epilogue: normalize, ELU, store ----
    const size_t obase = ((size_t)(b * NN + i0)) * NF;
#pragma unroll
    for (int mt = 0; mt < 2; mt++) {
        const int r0i = wm + mt * 16 + ar;
        const float rr0 = rsum[r0i];
        const float rr1 = rsum[r0i + 8];
        const float inv0 = rr0 > 0.f ? 1.f / rr0 : 0.f;
        const float inv1 = rr1 > 0.f ? 1.f / rr1 : 0.f;
#pragma unroll
        for (int nt = 0; nt < 4; nt++) {
            const int col = wn + nt * 8 + ac * 2;
            float x0 = acc[mt][nt][0] * inv0, x1 = acc[mt][nt][1] * inv0;
            float y0 = acc[mt][nt][2] * inv1, y1 = acc[mt][nt][3] * inv1;
            x0 = x0 > 0.f ? x0 : expm1f(x0);
            x1 = x1 > 0.f ? x1 : expm1f(x1);
            y0 = y0 > 0.f ? y0 : expm1f(y0);
            y1 = y1 > 0.f ? y1 : expm1f(y1);
            *(float2*)(out + obase + (size_t)r0i * NF + col)       = make_float2(x0, x1);
            *(float2*)(out + obase + (size_t)(r0i + 8) * NF + col) = make_float2(y0, y1);
        }
    }
}

// ---------------------------------------------------------------------------
extern "C" void kernel_launch(void* const* d_in, const int* in_sizes, int n_in,
                              void* d_out, int out_size) {
    const float* h   = (const float*)d_in[0];
    const int*   adj = (const int*)d_in[1];
    const float* W   = (const float*)d_in[2];
    const float* a   = (const float*)d_in[3];
    float* out = (float*)d_out;

    static_assert(SMEM_FLOATS * 4 < 114 * 1024, "smem too big for 2 CTAs/SM");
    cudaFuncSetAttribute(gat_k2, cudaFuncAttributeMaxDynamicSharedMemorySize,
                         SMEM_FLOATS * 4);

    gat_k1<<<(NB * NN) / K1R, 128>>>(h, W, a);
    gat_k2<<<NB * (NN / BM), 256, SMEM_FLOATS * 4>>>(adj, out);
}

// round 10
// speedup vs baseline: 1.5168x; 1.5168x over previous
#include <cuda_runtime.h>
#include <cuda_bf16.h>
#include <cstdint>

// ---------------------------------------------------------------------------
// GAT layer: B=4, N=4096, F_in=F_out=128
// K1: Wh (fp32) -> V (tf32), si, sj (pre-scaled by log2 e)
// K2: fused masked-softmax + PV via mma.sync tf32
//     - adj streamed as ballot-packed bitmasks (warp-cooperative, in-loop)
//     - P computed directly in A-fragment layout (STS.128 / LDS.128)
//     - cp.async double-buffered V staging; masks+PF double-buffered
// ---------------------------------------------------------------------------

#define NB   4
#define NN   4096
#define NF   128
#define BM   64
#define BN   64
#define NT   (NN / BN)

__device__ float g_V[(size_t)NB * NN * NF];
__device__ float g_si[NB * NN];     // scaled by LOG2E
__device__ float g_sj[NB * NN];     // scaled by LOG2E

#define LOG2E 1.4426950408889634f

__device__ __forceinline__ float to_tf32(float x) {
    float y;
    asm("cvt.rna.tf32.f32 %0, %1;" : "=f"(y) : "f"(x));
    return y;
}

// ---------------------------------------------------------------------------
// Kernel 1: Wh = h @ W, si, sj. 16 rows per block, 128 threads.
// ---------------------------------------------------------------------------
#define K1R 16
__global__ __launch_bounds__(128) void gat_k1(const float* __restrict__ h,
                                              const float* __restrict__ W,
                                              const float* __restrict__ a) {
    __shared__ float hs[K1R][128];
    __shared__ float red[2][K1R][4];
    const int tid = threadIdx.x;
    const int base = blockIdx.x * K1R;

#pragma unroll
    for (int r = 0; r < K1R; r++)
        hs[r][tid] = h[(size_t)(base + r) * NF + tid];
    __syncthreads();

    float acc[K1R];
#pragma unroll
    for (int r = 0; r < K1R; r++) acc[r] = 0.f;

#pragma unroll 4
    for (int f = 0; f < NF; f++) {
        const float w = W[f * NF + tid];
#pragma unroll
        for (int r = 0; r < K1R; r++)
            acc[r] = fmaf(hs[r][f], w, acc[r]);
    }

    const float ai = a[tid] * LOG2E;
    const float aj = a[NF + tid] * LOG2E;
    const int lane = tid & 31, warp = tid >> 5;

#pragma unroll
    for (int r = 0; r < K1R; r++) {
        g_V[(size_t)(base + r) * NF + tid] = to_tf32(acc[r]);
        float pi = acc[r] * ai;
        float pj = acc[r] * aj;
#pragma unroll
        for (int off = 16; off > 0; off >>= 1) {
            pi += __shfl_xor_sync(0xffffffffu, pi, off);
            pj += __shfl_xor_sync(0xffffffffu, pj, off);
        }
        if (lane == 0) { red[0][r][warp] = pi; red[1][r][warp] = pj; }
    }
    __syncthreads();
    if (tid < 32) {
        const int r = tid & 15, which = tid >> 4;
        const float s = red[which][r][0] + red[which][r][1] +
                        red[which][r][2] + red[which][r][3];
        (which ? g_sj : g_si)[base + r] = s;
    }
}

// ---------------------------------------------------------------------------
// Kernel 2
// smem: PF[2][4096] (P in A-fragment layout), Vs[2][64*136],
//       Msk[2][64][2] (ballot words: word[par] bit i <-> col 2i+par), rsum[64]
// ---------------------------------------------------------------------------
#define VS_STRIDE 136
#define PF_FLOATS 4096
#define VS_FLOATS (BN * VS_STRIDE)
#define MSK_WORDS 128
#define SMEM_FLOATS (2 * PF_FLOATS + 2 * VS_FLOATS + 2 * MSK_WORDS + 64)

#define CP_ASYNC16(dst_u32, src_ptr) \
    asm volatile("cp.async.cg.shared.global [%0], [%1], 16;" \
                 :: "r"(dst_u32), "l"(src_ptr))
#define CP_COMMIT()  asm volatile("cp.async.commit_group;" ::: "memory")
#define CP_WAIT1()   asm volatile("cp.async.wait_group 1;"  ::: "memory")

__device__ __forceinline__ float pval(float si, float sj, unsigned m) {
    float t = si + sj;
    t = t > 0.f ? t : 0.2f * t;
    float e;
    asm("ex2.approx.f32 %0, %1;" : "=f"(e) : "f"(t));
    return m ? e : 0.f;
}

__global__ __launch_bounds__(256, 2) void gat_k2(const int* __restrict__ adj,
                                                 float* __restrict__ out) {
    extern __shared__ float smem[];
    float*     PF   = smem;                         // 2 x 4096
    float*     Vs   = smem + 2 * PF_FLOATS;         // 2 x 64*136
    uint32_t*  Msk  = (uint32_t*)(Vs + 2 * VS_FLOATS); // 2 x 128 words
    float*     rsum = (float*)(Msk + 2 * MSK_WORDS);   // 64

    const int tid  = threadIdx.x;
    const int lane = tid & 31, warp = tid >> 5;
    const int b  = blockIdx.x >> 6;
    const int i0 = (blockIdx.x & 63) * BM;

    // fragment mapping (shared by P-phase and MMA-phase)
    const int k8 = warp;                 // P-phase k-chunk owned by this warp
    const int ar = lane >> 2;
    const int ac = lane & 3;
    const int c0 = k8 * 8 + ac;          // P-phase col (other col = c0+4)
    const int par = ac & 1;              // mask word parity
    const int bsh = c0 >> 1;             // bit for col c0; col c0+4 -> bsh+2

    const int*   adj_b = adj + ((size_t)(b * NN + i0)) * NN;
    const float* sjb   = g_sj + b * NN;
    const float* Vg    = g_V + (size_t)b * NN * NF;

    // si for this thread's 8 rows (tile-invariant)
    float sie[8];
#pragma unroll
    for (int ms = 0; ms < 4; ms++) {
        sie[ms * 2 + 0] = g_si[b * NN + i0 + 16 * ms + ar];
        sie[ms * 2 + 1] = g_si[b * NN + i0 + 16 * ms + ar + 8];
    }

    // MMA warp tiling: m32 x n32
    const int wm = (warp & 1) * 32;
    const int wn = (warp >> 1) * 32;
    const int ms0 = (warp & 1) * 2;

    // V staging (cp.async): thread copies 8 x 16B
    const int vr0 = tid >> 5;
    const int vc4 = (tid & 31) << 2;
    const uint32_t vs_base = (uint32_t)__cvta_generic_to_shared(Vs);

    // adj gen: warp packs rows 8*warp .. 8*warp+7; lane covers cols 2l,2l+1
    const int grow = 8 * warp;

    float acc[2][4][4];
#pragma unroll
    for (int mt = 0; mt < 2; mt++)
#pragma unroll
        for (int nt = 0; nt < 4; nt++)
#pragma unroll
            for (int j = 0; j < 4; j++) acc[mt][nt][j] = 0.f;
    float rs[8];
#pragma unroll
    for (int r = 0; r < 8; r++) rs[r] = 0.f;

    // ---- prologue: masks(0), V(0) cp.async into buf0, sj(0) ----
    {
        int2 va[8];
#pragma unroll
        for (int i = 0; i < 8; i++)
            va[i] = ((const int2*)(adj_b + (size_t)(grow + i) * NN))[lane];
#pragma unroll
        for (int i = 0; i < 8; i++) {
            const unsigned be = __ballot_sync(0xffffffffu, va[i].x != 0);
            const unsigned bo = __ballot_sync(0xffffffffu, va[i].y != 0);
            if (lane == i) {
                uint2 m2; m2.x = be; m2.y = bo;
                *(uint2*)(Msk + (grow + i) * 2) = m2;
            }
        }
#pragma unroll
        for (int q = 0; q < 8; q++) {
            const int vr = vr0 + q * 8;
            CP_ASYNC16(vs_base + (uint32_t)((vr * VS_STRIDE + vc4) * 4),
                       Vg + (size_t)vr * NF + vc4);
        }
        CP_COMMIT();
    }
    float sj0 = sjb[c0];
    float sj1 = sjb[c0 + 4];
    __syncthreads();   // masks(0) + sis visible

    for (int jt = 0; jt < NT; jt++) {
        const int buf = jt & 1;

        // ---- issue adj loads for jt+1 early (latency hidden by P-phase) ----
        int2 va[8];
        if (jt + 1 < NT) {
            const int j1 = (jt + 1) * BN;
#pragma unroll
            for (int i = 0; i < 8; i++)
                va[i] = ((const int2*)(adj_b + (size_t)(grow + i) * NN + j1))[lane];
        }

        // ---- P-phase: fragment-native, mask bits from smem words ----
        float* pf = PF + buf * PF_FLOATS;
        const uint32_t* mk = Msk + buf * MSK_WORDS;
#pragma unroll
        for (int ms = 0; ms < 4; ms++) {
            const uint32_t wA = mk[(16 * ms + ar) * 2 + par];
            const uint32_t wB = mk[(16 * ms + ar + 8) * 2 + par];
            const float p00 = pval(sie[ms * 2 + 0], sj0, (wA >> bsh) & 1u);
            const float p10 = pval(sie[ms * 2 + 1], sj0, (wB >> bsh) & 1u);
            const float p01 = pval(sie[ms * 2 + 0], sj1, (wA >> (bsh + 2)) & 1u);
            const float p11 = pval(sie[ms * 2 + 1], sj1, (wB >> (bsh + 2)) & 1u);
            rs[ms * 2 + 0] += p00 + p01;
            rs[ms * 2 + 1] += p10 + p11;
            float4 v; v.x = p00; v.y = p10; v.z = p01; v.w = p11;
            *(float4*)(pf + ((ms * 8 + k8) * 32 + lane) * 4) = v;
        }

        __syncthreads();   // syncA: PF[buf]+Msk[buf] reads done, PF visible

        // ---- publish masks(jt+1), stage V(jt+1), sj(jt+1) ----
        if (jt + 1 < NT) {
            const int j1 = (jt + 1) * BN;
            uint32_t* mkN = Msk + (buf ^ 1) * MSK_WORDS;
#pragma unroll
            for (int i = 0; i < 8; i++) {
                const unsigned be = __ballot_sync(0xffffffffu, va[i].x != 0);
                const unsigned bo = __ballot_sync(0xffffffffu, va[i].y != 0);
                if (lane == i) {
                    uint2 m2; m2.x = be; m2.y = bo;
                    *(uint2*)(mkN + (grow + i) * 2) = m2;
                }
            }
            const uint32_t vb = vs_base + (uint32_t)((buf ^ 1) * VS_FLOATS * 4);
#pragma unroll
            for (int q = 0; q < 8; q++) {
                const int vr = vr0 + q * 8;
                CP_ASYNC16(vb + (uint32_t)((vr * VS_STRIDE + vc4) * 4),
                           Vg + (size_t)(j1 + vr) * NF + vc4);
            }
            CP_COMMIT();
            sj0 = sjb[j1 + c0];
            sj1 = sjb[j1 + c0 + 4];
        } else {
            CP_COMMIT();   // keep group count uniform
        }
        CP_WAIT1();        // V(jt) landed; V(jt+1) still in flight

        // ---- MMA: acc += P(64x64) @ V(64x128) ----
        const float*    pfr = PF + buf * PF_FLOATS;
        const uint32_t* Vsu = (const uint32_t*)(Vs + buf * VS_FLOATS);
#pragma unroll
        for (int kk = 0; kk < 8; kk++) {
            uint4 af[2];
#pragma unroll
            for (int mt = 0; mt < 2; mt++)
                af[mt] = *(const uint4*)(pfr + (((ms0 + mt) * 8 + kk) * 32 + lane) * 4);
#pragma unroll
            for (int nt = 0; nt < 4; nt++) {
                const int n0 = wn + nt * 8;
                const uint32_t b0 = Vsu[(kk * 8 + ac)     * VS_STRIDE + n0 + ar];
                const uint32_t b1 = Vsu[(kk * 8 + ac + 4) * VS_STRIDE + n0 + ar];
#pragma unroll
                for (int mt = 0; mt < 2; mt++) {
                    asm volatile(
                        "mma.sync.aligned.m16n8k8.row.col.f32.tf32.tf32.f32 "
                        "{%0,%1,%2,%3}, {%4,%5,%6,%7}, {%8,%9}, {%0,%1,%2,%3};\n"
                        : "+f"(acc[mt][nt][0]), "+f"(acc[mt][nt][1]),
                          "+f"(acc[mt][nt][2]), "+f"(acc[mt][nt][3])
                        : "r"(af[mt].x), "r"(af[mt].y),
                          "r"(af[mt].z), "r"(af[mt].w),
                          "r"(b0), "r"(b1));
                }
            }
        }
        __syncthreads();   // syncB: MMA(jt) done; Msk/V(jt+1) published
    }

    // ---- row-sum reduction (reuse PF as Red[64][33]) ----
    float* Red = PF;
#pragma unroll
    for (int r8 = 0; r8 < 8; r8++) {
        const int row = 16 * (r8 >> 1) + ar + 8 * (r8 & 1);
        Red[row * 33 + k8 * 4 + ac] = rs[r8];
    }
    __syncthreads();
    if (tid < 64) {
        float s = 0.f;
#pragma unroll
        for (int k = 0; k < 32; k++) s += Red[tid * 33 + k];
        rsum[tid] = s;
    }
    __syncthreads();

    // ---- epilogue: normalize, ELU, store ----
    const size_t obase = ((size_t)(b * NN + i0)) * NF;
#pragma unroll
    for (int mt = 0; mt < 2; mt++) {
        const int r0i = wm + mt * 16 + ar;
        const float rr0 = rsum[r0i];
        const float rr1 = rsum[r0i + 8];
        const float inv0 = rr0 > 0.f ? 1.f / rr0 : 0.f;
        const float inv1 = rr1 > 0.f ? 1.f / rr1 : 0.f;
#pragma unroll
        for (int nt = 0; nt < 4; nt++) {
            const int col = wn + nt * 8 + ac * 2;
            float x0 = acc[mt][nt][0] * inv0, x1 = acc[mt][nt][1] * inv0;
            float y0 = acc[mt][nt][2] * inv1, y1 = acc[mt][nt][3] * inv1;
            x0 = x0 > 0.f ? x0 : expm1f(x0);
            x1 = x1 > 0.f ? x1 : expm1f(x1);
            y0 = y0 > 0.f ? y0 : expm1f(y0);
            y1 = y1 > 0.f ? y1 : expm1f(y1);
            *(float2*)(out + obase + (size_t)r0i * NF + col)       = make_float2(x0, x1);
            *(float2*)(out + obase + (size_t)(r0i + 8) * NF + col) = make_float2(y0, y1);
        }
    }
}

// ---------------------------------------------------------------------------
extern "C" void kernel_launch(void* const* d_in, const int* in_sizes, int n_in,
                              void* d_out, int out_size) {
    const float* h   = (const float*)d_in[0];
    const int*   adj = (const int*)d_in[1];
    const float* W   = (const float*)d_in[2];
    const float* a   = (const float*)d_in[3];
    float* out = (float*)d_out;

    static_assert(SMEM_FLOATS * 4 < 114 * 1024, "smem too big for 2 CTAs/SM");
    cudaFuncSetAttribute(gat_k2, cudaFuncAttributeMaxDynamicSharedMemorySize,
                         SMEM_FLOATS * 4);

    gat_k1<<<(NB * NN) / K1R, 128>>>(h, W, a);
    gat_k2<<<NB * (NN / BM), 256, SMEM_FLOATS * 4>>>(adj, out);
}

// round 11
// speedup vs baseline: 1.6817x; 1.1087x over previous
#include <cuda_runtime.h>
#include <cuda_bf16.h>
#include <cuda_fp16.h>
#include <cstdint>

// ---------------------------------------------------------------------------
// GAT layer: B=4, N=4096, F_in=F_out=128
// K1: Wh -> g_Vt (fp16, transposed [b][f][j]), si, sj (pre-scaled by log2 e)
// K2: fused masked-softmax + PV via mma.sync m16n8k16 fp16 (fp32 accum)
//     - P built directly as fp16 A-fragments with global shift 2^-10
//     - adj as ballot-packed col-order bitmasks
//     - cp.async double-buffered transposed-V staging (conflict-free B LDS)
// ---------------------------------------------------------------------------

#define NB   4
#define NN   4096
#define NF   128
#define BM   64
#define BN   64
#define NT   (NN / BN)

#define LOG2E 1.4426950408889634f
#define PSHIFT 10.0f

__device__ __half g_Vt[(size_t)NB * NF * NN];   // [b][f][j], fp16, 4 MB
__device__ float  g_si[NB * NN];     // scaled by LOG2E
__device__ float  g_sj[NB * NN];     // scaled by LOG2E

// ---------------------------------------------------------------------------
// Kernel 1: Wh = h @ W -> g_Vt (transposed fp16), si, sj
// ---------------------------------------------------------------------------
#define K1R 16
__global__ __launch_bounds__(128) void gat_k1(const float* __restrict__ h,
                                              const float* __restrict__ W,
                                              const float* __restrict__ a) {
    __shared__ float hs[K1R][128];
    __shared__ float red[2][K1R][4];
    const int tid = threadIdx.x;
    const int base = blockIdx.x * K1R;

#pragma unroll
    for (int r = 0; r < K1R; r++)
        hs[r][tid] = h[(size_t)(base + r) * NF + tid];
    __syncthreads();

    float acc[K1R];
#pragma unroll
    for (int r = 0; r < K1R; r++) acc[r] = 0.f;

#pragma unroll 4
    for (int f = 0; f < NF; f++) {
        const float w = W[f * NF + tid];
#pragma unroll
        for (int r = 0; r < K1R; r++)
            acc[r] = fmaf(hs[r][f], w, acc[r]);
    }

    // transposed fp16 write: thread owns feature f = tid, 16 consecutive j
    {
        const int b = base / NN;
        const int j_in = base % NN;
        __half2 hv[8];
#pragma unroll
        for (int q = 0; q < 8; q++)
            hv[q] = __floats2half2_rn(acc[2 * q], acc[2 * q + 1]);
        __half* dst = g_Vt + ((size_t)b * NF + tid) * NN + j_in;
        ((uint4*)dst)[0] = ((uint4*)hv)[0];
        ((uint4*)dst)[1] = ((uint4*)hv)[1];
    }

    const float ai = a[tid] * LOG2E;
    const float aj = a[NF + tid] * LOG2E;
    const int lane = tid & 31, warp = tid >> 5;

#pragma unroll
    for (int r = 0; r < K1R; r++) {
        float pi = acc[r] * ai;
        float pj = acc[r] * aj;
#pragma unroll
        for (int off = 16; off > 0; off >>= 1) {
            pi += __shfl_xor_sync(0xffffffffu, pi, off);
            pj += __shfl_xor_sync(0xffffffffu, pj, off);
        }
        if (lane == 0) { red[0][r][warp] = pi; red[1][r][warp] = pj; }
    }
    __syncthreads();
    if (tid < 32) {
        const int r = tid & 15, which = tid >> 4;
        const float s = red[which][r][0] + red[which][r][1] +
                        red[which][r][2] + red[which][r][3];
        (which ? g_sj : g_si)[base + r] = s;
    }
}

// ---------------------------------------------------------------------------
// Kernel 2
// smem: PF[2048 floats] = fp16 A-fragments (single buffer),
//       Vsw[2][128 rows x 36 words] transposed V fp16 (stride 144B),
//       Msk[64][2] col-order ballot words, rsum[64]
// ---------------------------------------------------------------------------
#define PF_FLOATS 2048
#define VT_WSTRIDE 36                    // 36 words = 72 halves = 144 B
#define VS_WORDS  (NF * VT_WSTRIDE)      // 4608 words per buffer
#define SMEM_FLOATS (PF_FLOATS + 2 * VS_WORDS + 2 * 64 + 64)

#define CP_ASYNC16(dst_u32, src_ptr) \
    asm volatile("cp.async.cg.shared.global [%0], [%1], 16;" \
                 :: "r"(dst_u32), "l"(src_ptr))
#define CP_COMMIT()  asm volatile("cp.async.commit_group;" ::: "memory")
#define CP_WAIT0()   asm volatile("cp.async.wait_group 0;"  ::: "memory")

// p = exp2(leaky(si+sj) - PSHIFT), zeroed (2^-40) when mask bit clear
__device__ __forceinline__ float pv(float si, float sj, uint32_t w, int bit) {
    float t = si + sj;
    float u = fminf(t, 0.f);
    float arg = fmaf(u, -0.8f, t) - PSHIFT;     // leaky then shift
    arg = ((w >> bit) & 1u) ? arg : -40.f;
    float e;
    asm("ex2.approx.f32 %0, %1;" : "=f"(e) : "f"(arg));
    return e;
}

#define MMA16(accv, af, b0, b1)                                            \
    asm volatile(                                                          \
        "mma.sync.aligned.m16n8k16.row.col.f32.f16.f16.f32 "               \
        "{%0,%1,%2,%3}, {%4,%5,%6,%7}, {%8,%9}, {%0,%1,%2,%3};\n"          \
        : "+f"(accv[0]), "+f"(accv[1]), "+f"(accv[2]), "+f"(accv[3])       \
        : "r"(af.x), "r"(af.y), "r"(af.z), "r"(af.w), "r"(b0), "r"(b1))

__global__ __launch_bounds__(256, 2) void gat_k2(const int* __restrict__ adj,
                                                 float* __restrict__ out) {
    extern __shared__ float smem[];
    float*     PF   = smem;                              // 2048 floats
    uint32_t*  Vsw  = (uint32_t*)(smem + PF_FLOATS);     // 2 x 4608 words
    uint32_t*  Msk  = Vsw + 2 * VS_WORDS;                // 128 words
    float*     rsum = (float*)(Msk + 2 * 64);            // 64

    const int tid  = threadIdx.x;
    const int lane = tid & 31, warp = tid >> 5;
    const int b  = blockIdx.x >> 6;
    const int i0 = (blockIdx.x & 63) * BM;

    // producer fragment mapping
    const int kw = warp & 3;             // kk16 chunk 0..3 owned for P
    const int mh = warp >> 2;            // ms pair {2mh, 2mh+1}
    const int ar = lane >> 2;
    const int ac = lane & 3;
    const int c00 = 16 * kw + 2 * ac;    // first col of fragment pair
    const int bb  = 16 * (kw & 1) + 2 * ac;  // bit base in 32-col mask word

    // consumer tiling (m32 x n32)
    const int wm  = (warp & 1) * 32;
    const int wn  = (warp >> 1) * 32;
    const int ms0 = (warp & 1) * 2;

    const int*    adj_b = adj + ((size_t)(b * NN + i0)) * NN;
    const float*  sjb   = g_sj + b * NN;
    const __half* Vtg   = g_Vt + (size_t)b * NF * NN;

    // si rows (tile-invariant): 32mh + 16msl + 8rh + ar
    float sie[4];
#pragma unroll
    for (int q = 0; q < 4; q++)
        sie[q] = g_si[b * NN + i0 + 32 * mh + 16 * (q >> 1) + 8 * (q & 1) + ar];

    // V staging: thread copies 4 x 16B; row = f, 8 chunks of 16B per row
    const int vrow = tid >> 1;
    const int vch0 = (tid & 1) * 4;
    const uint32_t vs_base = (uint32_t)__cvta_generic_to_shared(Vsw);

    const int grow = 8 * warp;           // adj rows owned by this warp

    float acc[2][4][4];
#pragma unroll
    for (int mt = 0; mt < 2; mt++)
#pragma unroll
        for (int nt = 0; nt < 4; nt++)
#pragma unroll
            for (int j = 0; j < 4; j++) acc[mt][nt][j] = 0.f;
    float rs[4] = {0.f, 0.f, 0.f, 0.f};

    // ---- prologue: masks(0), V(0) via cp.async buf0, sj(0) regs ----
#pragma unroll
    for (int i = 0; i < 8; i++) {
        const int* rowp = adj_b + (size_t)(grow + i) * NN;
        const int a0 = rowp[lane];
        const int a1 = rowp[lane + 32];
        const unsigned w0 = __ballot_sync(0xffffffffu, a0 != 0);
        const unsigned w1 = __ballot_sync(0xffffffffu, a1 != 0);
        if (lane == i) {
            uint2 m; m.x = w0; m.y = w1;
            *(uint2*)(Msk + (grow + i) * 2) = m;
        }
    }
#pragma unroll
    for (int q = 0; q < 4; q++)
        CP_ASYNC16(vs_base + (uint32_t)((vrow * VT_WSTRIDE + (vch0 + q) * 4) * 4),
                   Vtg + (size_t)vrow * NN + (vch0 + q) * 8);
    CP_COMMIT();
    float2 sjA = *(const float2*)(sjb + c00);
    float2 sjB = *(const float2*)(sjb + c00 + 8);
    __syncthreads();   // masks(0) visible

    for (int jt = 0; jt < NT; jt++) {
        const int buf = jt & 1;

        // ---- adj loads for jt+1 (latency hidden under P-phase) ----
        int av[16];
        if (jt + 1 < NT) {
            const int j1 = (jt + 1) * BN;
#pragma unroll
            for (int i = 0; i < 8; i++) {
                const int* rowp = adj_b + (size_t)(grow + i) * NN + j1;
                av[2 * i]     = rowp[lane];
                av[2 * i + 1] = rowp[lane + 32];
            }
        }

        // ---- P-phase: build fp16 A-fragments directly ----
#pragma unroll
        for (int msl = 0; msl < 2; msl++) {
            const int ms = 2 * mh + msl;
            const int r0 = 16 * ms + ar;
            const uint32_t w0 = Msk[r0 * 2 + (kw >> 1)];
            const uint32_t w1 = Msk[(r0 + 8) * 2 + (kw >> 1)];
            const float si0 = sie[msl * 2 + 0];
            const float si1 = sie[msl * 2 + 1];
            const float p00 = pv(si0, sjA.x, w0, bb);
            const float p01 = pv(si0, sjA.y, w0, bb + 1);
            const float p02 = pv(si0, sjB.x, w0, bb + 8);
            const float p03 = pv(si0, sjB.y, w0, bb + 9);
            const float p10 = pv(si1, sjA.x, w1, bb);
            const float p11 = pv(si1, sjA.y, w1, bb + 1);
            const float p12 = pv(si1, sjB.x, w1, bb + 8);
            const float p13 = pv(si1, sjB.y, w1, bb + 9);
            rs[msl * 2 + 0] += (p00 + p01) + (p02 + p03);
            rs[msl * 2 + 1] += (p10 + p11) + (p12 + p13);
            uint4 fr;
            __half2 t;
            t = __floats2half2_rn(p00, p01); fr.x = *(uint32_t*)&t;
            t = __floats2half2_rn(p10, p11); fr.y = *(uint32_t*)&t;
            t = __floats2half2_rn(p02, p03); fr.z = *(uint32_t*)&t;
            t = __floats2half2_rn(p12, p13); fr.w = *(uint32_t*)&t;
            ((uint4*)PF)[(ms * 4 + kw) * 32 + lane] = fr;
        }

        CP_WAIT0();        // V(jt) fully landed (this thread's copies)
        __syncthreads();   // all threads' waits done -> V+PF visible to all

        // ---- publish tile jt+1: masks, V cp.async, sj regs ----
        if (jt + 1 < NT) {
            const int j1 = (jt + 1) * BN;
#pragma unroll
            for (int i = 0; i < 8; i++) {
                const unsigned w0 = __ballot_sync(0xffffffffu, av[2 * i] != 0);
                const unsigned w1 = __ballot_sync(0xffffffffu, av[2 * i + 1] != 0);
                if (lane == i) {
                    uint2 m; m.x = w0; m.y = w1;
                    *(uint2*)(Msk + (grow + i) * 2) = m;
                }
            }
            const uint32_t vb = vs_base + (uint32_t)((buf ^ 1) * VS_WORDS * 4);
#pragma unroll
            for (int q = 0; q < 4; q++)
                CP_ASYNC16(vb + (uint32_t)((vrow * VT_WSTRIDE + (vch0 + q) * 4) * 4),
                           Vtg + (size_t)vrow * NN + j1 + (vch0 + q) * 8);
            CP_COMMIT();
            sjA = *(const float2*)(sjb + j1 + c00);
            sjB = *(const float2*)(sjb + j1 + c00 + 8);
        }

        // ---- MMA: acc += P(64x64) @ V(64x128), fp16 k16 ----
        const uint4*    pfr = (const uint4*)PF;
        const uint32_t* vb2 = Vsw + buf * VS_WORDS;
#pragma unroll
        for (int kk = 0; kk < 4; kk++) {
            const uint4 af0 = pfr[((ms0 + 0) * 4 + kk) * 32 + lane];
            const uint4 af1 = pfr[((ms0 + 1) * 4 + kk) * 32 + lane];
#pragma unroll
            for (int nt = 0; nt < 4; nt++) {
                const int n = wn + nt * 8 + ar;
                const uint32_t b0 = vb2[n * VT_WSTRIDE + kk * 8 + ac];
                const uint32_t b1 = vb2[n * VT_WSTRIDE + kk * 8 + ac + 4];
                MMA16(acc[0][nt], af0, b0, b1);
                MMA16(acc[1][nt], af1, b0, b1);
            }
        }
        __syncthreads();   // MMA(jt) done before P(jt+1) overwrites PF/Msk
    }

    // ---- row-sum reduction (reuse PF as Red[64][17]) ----
    float* Red = PF;
#pragma unroll
    for (int q = 0; q < 4; q++) {
        const int row = 32 * mh + 16 * (q >> 1) + 8 * (q & 1) + ar;
        Red[row * 17 + kw * 4 + ac] = rs[q];
    }
    __syncthreads();
    if (tid < 64) {
        float s = 0.f;
#pragma unroll
        for (int k = 0; k < 16; k++) s += Red[tid * 17 + k];
        rsum[tid] = s;
    }
    __syncthreads();

    // ---- epilogue: normalize, ELU, store ----
    const size_t obase = ((size_t)(b * NN + i0)) * NF;
#pragma unroll
    for (int mt = 0; mt < 2; mt++) {
        const int r0i = wm + mt * 16 + ar;
        const float rr0 = rsum[r0i];
        const float rr1 = rsum[r0i + 8];
        const float inv0 = rr0 > 0.f ? 1.f / rr0 : 0.f;
        const float inv1 = rr1 > 0.f ? 1.f / rr1 : 0.f;
#pragma unroll
        for (int nt = 0; nt < 4; nt++) {
            const int col = wn + nt * 8 + ac * 2;
            float x0 = acc[mt][nt][0] * inv0, x1 = acc[mt][nt][1] * inv0;
            float y0 = acc[mt][nt][2] * inv1, y1 = acc[mt][nt][3] * inv1;
            x0 = x0 > 0.f ? x0 : expm1f(x0);
            x1 = x1 > 0.f ? x1 : expm1f(x1);
            y0 = y0 > 0.f ? y0 : expm1f(y0);
            y1 = y1 > 0.f ? y1 : expm1f(y1);
            *(float2*)(out + obase + (size_t)r0i * NF + col)       = make_float2(x0, x1);
            *(float2*)(out + obase + (size_t)(r0i + 8) * NF + col) = make_float2(y0, y1);
        }
    }
}

// ---------------------------------------------------------------------------
extern "C" void kernel_launch(void* const* d_in, const int* in_sizes, int n_in,
                              void* d_out, int out_size) {
    const float* h   = (const float*)d_in[0];
    const int*   adj = (const int*)d_in[1];
    const float* W   = (const float*)d_in[2];
    const float* a   = (const float*)d_in[3];
    float* out = (float*)d_out;

    static_assert(SMEM_FLOATS * 4 < 114 * 1024, "smem too big for 2 CTAs/SM");
    cudaFuncSetAttribute(gat_k2, cudaFuncAttributeMaxDynamicSharedMemorySize,
                         SMEM_FLOATS * 4);

    gat_k1<<<(NB * NN) / K1R, 128>>>(h, W, a);
    gat_k2<<<NB * (NN / BM), 256, SMEM_FLOATS * 4>>>(adj, out);
}

// round 13
// speedup vs baseline: 1.9656x; 1.1689x over previous
#include <cuda_runtime.h>
#include <cuda_bf16.h>
#include <cuda_fp16.h>
#include <cstdint>

// ---------------------------------------------------------------------------
// GAT layer: B=4, N=4096, F_in=F_out=128
// K1: Wh = h@W via m16n8k8 tf32 MMA -> g_Vt (fp16, transposed [b][f][j]),
//     si, sj (pre-scaled by log2 e)
// K2: fused masked-softmax + PV via mma.sync m16n8k16 fp16 (fp32 accum)
//     - P built directly as fp16 A-fragments, shift 2^-10
//     - adj as ballot-packed col-order bitmasks
//     - B-fragments via ldmatrix.m8n8.x4 (conflict-free)
//     - softmax denominators via ones-column MMA (no smem reduction)
// ---------------------------------------------------------------------------

#define NB   4
#define NN   4096
#define NF   128
#define BM   64
#define BN   64
#define NT   (NN / BN)

#define LOG2E 1.4426950408889634f
#define PSHIFT 10.0f

__device__ __half g_Vt[(size_t)NB * NF * NN];   // [b][f][j], fp16, 4 MB
__device__ float  g_si[NB * NN];     // scaled by LOG2E
__device__ float  g_sj[NB * NN];     // scaled by LOG2E

#define CP_ASYNC16(dst_u32, src_ptr) \
    asm volatile("cp.async.cg.shared.global [%0], [%1], 16;" \
                 :: "r"(dst_u32), "l"(src_ptr))
#define CP_COMMIT()  asm volatile("cp.async.commit_group;" ::: "memory")
#define CP_WAIT0()   asm volatile("cp.async.wait_group 0;"  ::: "memory")

__device__ __forceinline__ uint32_t tf32u(float x) {
    float y;
    asm("cvt.rna.tf32.f32 %0, %1;" : "=f"(y) : "f"(x));
    return __float_as_uint(y);
}

// ---------------------------------------------------------------------------
// Kernel 1: Wh = h @ W via tf32 MMA; outputs transposed fp16 V, si, sj.
// Grid 256 blocks x 256 threads; block owns 64 rows; warp = m16 x n64.
// ---------------------------------------------------------------------------
#define HS_S 132     // 132 mod 32 = 4 -> A-frag scalar LDS conflict-free
#define WS_S 136     // 136 mod 32 = 8 -> B-frag scalar LDS conflict-free
#define K1_SMEM_FLOATS (64 * HS_S + 128 * WS_S + 256)

__global__ __launch_bounds__(256, 2) void gat_k1(const float* __restrict__ h,
                                                 const float* __restrict__ W,
                                                 const float* __restrict__ a) {
    extern __shared__ float sm1[];
    float* hs  = sm1;                 // 64 x 132
    float* Ws  = sm1 + 64 * HS_S;     // 128 x 136
    float* red = Ws + 128 * WS_S;     // 64 x 2 x 2

    const int tid  = threadIdx.x;
    const int lane = tid & 31, warp = tid >> 5;
    const int gr   = blockIdx.x * 64;            // global row base

    // ---- stage h tile (64x128 f32 = 2048 16B-chunks) and W (128x128 f32 =
    //      4096 chunks) via cp.async, linear chunk distribution ----
    const uint32_t hs_b = (uint32_t)__cvta_generic_to_shared(hs);
    const uint32_t ws_b = (uint32_t)__cvta_generic_to_shared(Ws);
    {
        const float* hg = h + (size_t)gr * NF;
#pragma unroll
        for (int q = 0; q < 8; q++) {
            const int c = tid + q * 256;           // 0..2047
            const int r = c >> 5, ch = c & 31;
            CP_ASYNC16(hs_b + (uint32_t)((r * HS_S + ch * 4) * 4),
                       hg + r * NF + ch * 4);
        }
#pragma unroll
        for (int q = 0; q < 16; q++) {
            const int c = tid + q * 256;           // 0..4095
            const int r = c >> 5, ch = c & 31;
            CP_ASYNC16(ws_b + (uint32_t)((r * WS_S + ch * 4) * 4),
                       W + r * NF + ch * 4);
        }
    }
    CP_COMMIT(); CP_WAIT0();
    __syncthreads();

    const int wm  = (warp & 3) * 16;   // m-stripe
    const int wnh = warp >> 2;         // n-half (0/1)
    const int ar  = lane >> 2, ac = lane & 3;

    float acc[8][4];
#pragma unroll
    for (int nt = 0; nt < 8; nt++)
#pragma unroll
        for (int e = 0; e < 4; e++) acc[nt][e] = 0.f;

#pragma unroll
    for (int kk = 0; kk < 16; kk++) {
        const int k0 = kk * 8;
        const uint32_t a0 = tf32u(hs[(wm + ar)     * HS_S + k0 + ac]);
        const uint32_t a1 = tf32u(hs[(wm + ar + 8) * HS_S + k0 + ac]);
        const uint32_t a2 = tf32u(hs[(wm + ar)     * HS_S + k0 + ac + 4]);
        const uint32_t a3 = tf32u(hs[(wm + ar + 8) * HS_S + k0 + ac + 4]);
#pragma unroll
        for (int nt = 0; nt < 8; nt++) {
            const int n0 = wnh * 64 + nt * 8;
            const uint32_t b0 = tf32u(Ws[(k0 + ac)     * WS_S + n0 + ar]);
            const uint32_t b1 = tf32u(Ws[(k0 + ac + 4) * WS_S + n0 + ar]);
            asm volatile(
                "mma.sync.aligned.m16n8k8.row.col.f32.tf32.tf32.f32 "
                "{%0,%1,%2,%3}, {%4,%5,%6,%7}, {%8,%9}, {%0,%1,%2,%3};\n"
                : "+f"(acc[nt][0]), "+f"(acc[nt][1]),
                  "+f"(acc[nt][2]), "+f"(acc[nt][3])
                : "r"(a0), "r"(a1), "r"(a2), "r"(a3), "r"(b0), "r"(b1));
        }
    }

    // ---- epilogue: transposed fp16 V, si/sj partial dots ----
    const int b   = gr >> 12;          // gr / NN
    const int jin = gr & (NN - 1);
    const int r0  = wm + ar, r1 = wm + ar + 8;
    __half* vt = g_Vt + (size_t)b * NF * NN + jin;

    float pi0 = 0.f, pi1 = 0.f, pj0 = 0.f, pj1 = 0.f;
#pragma unroll
    for (int nt = 0; nt < 8; nt++) {
        const int c0 = wnh * 64 + nt * 8 + 2 * ac;
        const float ai0 = a[c0] * LOG2E,        ai1 = a[c0 + 1] * LOG2E;
        const float aj0 = a[NF + c0] * LOG2E,   aj1 = a[NF + c0 + 1] * LOG2E;
        vt[(size_t)c0 * NN + r0]       = __float2half_rn(acc[nt][0]);
        vt[(size_t)(c0 + 1) * NN + r0] = __float2half_rn(acc[nt][1]);
        vt[(size_t)c0 * NN + r1]       = __float2half_rn(acc[nt][2]);
        vt[(size_t)(c0 + 1) * NN + r1] = __float2half_rn(acc[nt][3]);
        pi0 += acc[nt][0] * ai0 + acc[nt][1] * ai1;
        pi1 += acc[nt][2] * ai0 + acc[nt][3] * ai1;
        pj0 += acc[nt][0] * aj0 + acc[nt][1] * aj1;
        pj1 += acc[nt][2] * aj0 + acc[nt][3] * aj1;
    }
#pragma unroll
    for (int off = 1; off <= 2; off <<= 1) {
        pi0 += __shfl_xor_sync(0xffffffffu, pi0, off);
        pi1 += __shfl_xor_sync(0xffffffffu, pi1, off);
        pj0 += __shfl_xor_sync(0xffffffffu, pj0, off);
        pj1 += __shfl_xor_sync(0xffffffffu, pj1, off);
    }
    if (ac == 0) {
        red[r0 * 4 + wnh * 2 + 0] = pi0;
        red[r0 * 4 + wnh * 2 + 1] = pj0;
        red[r1 * 4 + wnh * 2 + 0] = pi1;
        red[r1 * 4 + wnh * 2 + 1] = pj1;
    }
    __syncthreads();
    if (tid < 128) {
        const int row = tid >> 1, which = tid & 1;
        const float s = red[row * 4 + which] + red[row * 4 + 2 + which];
        (which ? g_sj : g_si)[gr + row] = s;
    }
}

// ---------------------------------------------------------------------------
// Kernel 2
// smem: PF[2048 floats] fp16 A-frags, Vsw[2][128 x 36 words] transposed V,
//       Msk[64][2] col-order ballot words
// ---------------------------------------------------------------------------
#define PF_FLOATS 2048
#define VT_WSTRIDE 36                    // 36 words = 144 B (16B aligned rows)
#define VS_WORDS  (NF * VT_WSTRIDE)
#define SMEM_FLOATS (PF_FLOATS + 2 * VS_WORDS + 2 * 64)

#define ONE2 0x3C003C00u                 // fp16 (1.0, 1.0)

#define LDSM4(r0, r1, r2, r3, addr) \
    asm volatile("ldmatrix.sync.aligned.m8n8.x4.shared.b16 {%0,%1,%2,%3}, [%4];" \
                 : "=r"(r0), "=r"(r1), "=r"(r2), "=r"(r3) : "r"(addr))

__device__ __forceinline__ float pv(float si, float sj, uint32_t w, int bit) {
    float t = si + sj;
    float u = fminf(t, 0.f);
    float arg = fmaf(u, -0.8f, t) - PSHIFT;     // leaky then shift
    arg = ((w >> bit) & 1u) ? arg : -40.f;
    float e;
    asm("ex2.approx.f32 %0, %1;" : "=f"(e) : "f"(arg));
    return e;
}

#define MMA16(accv, af, b0, b1)                                            \
    asm volatile(                                                          \
        "mma.sync.aligned.m16n8k16.row.col.f32.f16.f16.f32 "               \
        "{%0,%1,%2,%3}, {%4,%5,%6,%7}, {%8,%9}, {%0,%1,%2,%3};\n"          \
        : "+f"(accv[0]), "+f"(accv[1]), "+f"(accv[2]), "+f"(accv[3])       \
        : "r"(af.x), "r"(af.y), "r"(af.z), "r"(af.w), "r"(b0), "r"(b1))

__global__ __launch_bounds__(256, 2) void gat_k2(const int* __restrict__ adj,
                                                 float* __restrict__ out) {
    extern __shared__ float smem[];
    float*     PF   = smem;                              // 2048 floats
    uint32_t*  Vsw  = (uint32_t*)(smem + PF_FLOATS);     // 2 x 4608 words
    uint32_t*  Msk  = Vsw + 2 * VS_WORDS;                // 128 words

    const int tid  = threadIdx.x;
    const int lane = tid & 31, warp = tid >> 5;
    const int b  = blockIdx.x >> 6;
    const int i0 = (blockIdx.x & 63) * BM;

    // producer fragment mapping
    const int kw = warp & 3;             // kk16 chunk 0..3 owned for P
    const int mh = warp >> 2;            // ms pair {2mh, 2mh+1}
    const int ar = lane >> 2;
    const int ac = lane & 3;
    const int c00 = 16 * kw + 2 * ac;    // first col of fragment pair
    const int bb  = 16 * (kw & 1) + 2 * ac;  // bit base in 32-col mask word

    // consumer tiling (m32 x n32)
    const int wm  = (warp & 1) * 32;
    const int wn  = (warp >> 1) * 32;
    const int ms0 = (warp & 1) * 2;

    const int*    adj_b = adj + ((size_t)(b * NN + i0)) * NN;
    const float*  sjb   = g_sj + b * NN;
    const __half* Vtg   = g_Vt + (size_t)b * NF * NN;

    // si rows (tile-invariant)
    float sie[4];
#pragma unroll
    for (int q = 0; q < 4; q++)
        sie[q] = g_si[b * NN + i0 + 32 * mh + 16 * (q >> 1) + 8 * (q & 1) + ar];

    // V staging: thread copies 4 x 16B
    const int vrow = tid >> 1;
    const int vch0 = (tid & 1) * 4;
    const uint32_t vs_base = (uint32_t)__cvta_generic_to_shared(Vsw);

    // ldmatrix per-thread invariant word offset
    const int mrow = lane & 7, mid = lane >> 3;
    const int ldOff = (wn + (mid >> 1) * 8 + mrow) * VT_WSTRIDE + (mid & 1) * 4;

    const int grow = 8 * warp;           // adj rows owned by this warp

    float acc[2][4][4];
#pragma unroll
    for (int mt = 0; mt < 2; mt++)
#pragma unroll
        for (int nt = 0; nt < 4; nt++)
#pragma unroll
            for (int j = 0; j < 4; j++) acc[mt][nt][j] = 0.f;
    float acc_s[2][4];
#pragma unroll
    for (int mt = 0; mt < 2; mt++)
#pragma unroll
        for (int j = 0; j < 4; j++) acc_s[mt][j] = 0.f;

    // ---- prologue: masks(0), V(0) via cp.async buf0, sj(0) regs ----
#pragma unroll
    for (int i = 0; i < 8; i++) {
        const int* rowp = adj_b + (size_t)(grow + i) * NN;
        const int a0 = rowp[lane];
        const int a1 = rowp[lane + 32];
        const unsigned w0 = __ballot_sync(0xffffffffu, a0 != 0);
        const unsigned w1 = __ballot_sync(0xffffffffu, a1 != 0);
        if (lane == i) {
            uint2 m; m.x = w0; m.y = w1;
            *(uint2*)(Msk + (grow + i) * 2) = m;
        }
    }
#pragma unroll
    for (int q = 0; q < 4; q++)
        CP_ASYNC16(vs_base + (uint32_t)((vrow * VT_WSTRIDE + (vch0 + q) * 4) * 4),
                   Vtg + (size_t)vrow * NN + (vch0 + q) * 8);
    CP_COMMIT();
    float2 sjA = *(const float2*)(sjb + c00);
    float2 sjB = *(const float2*)(sjb + c00 + 8);
    __syncthreads();   // masks(0) visible

    for (int jt = 0; jt < NT; jt++) {
        const int buf = jt & 1;

        // ---- adj loads for jt+1 (latency hidden under P-phase) ----
        int av[16];
        if (jt + 1 < NT) {
            const int j1 = (jt + 1) * BN;
#pragma unroll
            for (int i = 0; i < 8; i++) {
                const int* rowp = adj_b + (size_t)(grow + i) * NN + j1;
                av[2 * i]     = rowp[lane];
                av[2 * i + 1] = rowp[lane + 32];
            }
        }

        // ---- P-phase: build fp16 A-fragments directly ----
#pragma unroll
        for (int msl = 0; msl < 2; msl++) {
            const int ms = 2 * mh + msl;
            const int r0 = 16 * ms + ar;
            const uint32_t w0 = Msk[r0 * 2 + (kw >> 1)];
            const uint32_t w1 = Msk[(r0 + 8) * 2 + (kw >> 1)];
            const float si0 = sie[msl * 2 + 0];
            const float si1 = sie[msl * 2 + 1];
            const float p00 = pv(si0, sjA.x, w0, bb);
            const float p01 = pv(si0, sjA.y, w0, bb + 1);
            const float p02 = pv(si0, sjB.x, w0, bb + 8);
            const float p03 = pv(si0, sjB.y, w0, bb + 9);
            const float p10 = pv(si1, sjA.x, w1, bb);
            const float p11 = pv(si1, sjA.y, w1, bb + 1);
            const float p12 = pv(si1, sjB.x, w1, bb + 8);
            const float p13 = pv(si1, sjB.y, w1, bb + 9);
            uint4 fr;
            __half2 t;
            t = __floats2half2_rn(p00, p01); fr.x = *(uint32_t*)&t;
            t = __floats2half2_rn(p10, p11); fr.y = *(uint32_t*)&t;
            t = __floats2half2_rn(p02, p03); fr.z = *(uint32_t*)&t;
            t = __floats2half2_rn(p12, p13); fr.w = *(uint32_t*)&t;
            ((uint4*)PF)[(ms * 4 + kw) * 32 + lane] = fr;
        }

        CP_WAIT0();        // V(jt) fully landed (this thread's copies)
        __syncthreads();   // all threads' waits done -> V+PF visible to all

        // ---- publish tile jt+1: masks, V cp.async, sj regs ----
        if (jt + 1 < NT) {
            const int j1 = (jt + 1) * BN;
#pragma unroll
            for (int i = 0; i < 8; i++) {
                const unsigned w0 = __ballot_sync(0xffffffffu, av[2 * i] != 0);
                const unsigned w1 = __ballot_sync(0xffffffffu, av[2 * i + 1] != 0);
                if (lane == i) {
                    uint2 m; m.x = w0; m.y = w1;
                    *(uint2*)(Msk + (grow + i) * 2) = m;
                }
            }
            const uint32_t vb = vs_base + (uint32_t)((buf ^ 1) * VS_WORDS * 4);
#pragma unroll
            for (int q = 0; q < 4; q++)
                CP_ASYNC16(vb + (uint32_t)((vrow * VT_WSTRIDE + (vch0 + q) * 4) * 4),
                           Vtg + (size_t)vrow * NN + j1 + (vch0 + q) * 8);
            CP_COMMIT();
            sjA = *(const float2*)(sjb + j1 + c00);
            sjB = *(const float2*)(sjb + j1 + c00 + 8);
        }

        // ---- MMA: acc += P(64x64) @ V(64x128); acc_s += P @ ones ----
        const uint4*   pfr  = (const uint4*)PF;
        const uint32_t vbuf = vs_base + (uint32_t)(buf * VS_WORDS * 4);
#pragma unroll
        for (int kk = 0; kk < 4; kk++) {
            const uint4 af0 = pfr[((ms0 + 0) * 4 + kk) * 32 + lane];
            const uint4 af1 = pfr[((ms0 + 1) * 4 + kk) * 32 + lane];
            uint32_t bA0, bA1, bA2, bA3, bB0, bB1, bB2, bB3;
            LDSM4(bA0, bA1, bA2, bA3,
                  vbuf + (uint32_t)((ldOff + kk * 8) * 4));
            LDSM4(bB0, bB1, bB2, bB3,
                  vbuf + (uint32_t)((ldOff + 16 * VT_WSTRIDE + kk * 8) * 4));
            MMA16(acc[0][0], af0, bA0, bA1);
            MMA16(acc[1][0], af1, bA0, bA1);
            MMA16(acc[0][1], af0, bA2, bA3);
            MMA16(acc[1][1], af1, bA2, bA3);
            MMA16(acc[0][2], af0, bB0, bB1);
            MMA16(acc[1][2], af1, bB0, bB1);
            MMA16(acc[0][3], af0, bB2, bB3);
            MMA16(acc[1][3], af1, bB2, bB3);
            MMA16(acc_s[0], af0, ONE2, ONE2);
            MMA16(acc_s[1], af1, ONE2, ONE2);
        }
        __syncthreads();   // MMA(jt) done before P(jt+1) overwrites PF/Msk
    }

    // ---- epilogue: normalize (denominators live in acc_s), ELU, store ----
    const size_t obase = ((size_t)(b * NN + i0)) * NF;
#pragma unroll
    for (int mt = 0; mt < 2; mt++) {
        const int r0i = wm + mt * 16 + ar;
        const float rr0 = acc_s[mt][0];
        const float rr1 = acc_s[mt][2];
        const float inv0 = rr0 > 0.f ? 1.f / rr0 : 0.f;
        const float inv1 = rr1 > 0.f ? 1.f / rr1 : 0.f;
#pragma unroll
        for (int nt = 0; nt < 4; nt++) {
            const int col = wn + nt * 8 + ac * 2;
            float x0 = acc[mt][nt][0] * inv0, x1 = acc[mt][nt][1] * inv0;
            float y0 = acc[mt][nt][2] * inv1, y1 = acc[mt][nt][3] * inv1;
            x0 = x0 > 0.f ? x0 : expm1f(x0);
            x1 = x1 > 0.f ? x1 : expm1f(x1);
            y0 = y0 > 0.f ? y0 : expm1f(y0);
            y1 = y1 > 0.f ? y1 : expm1f(y1);
            *(float2*)(out + obase + (size_t)r0i * NF + col)       = make_float2(x0, x1);
            *(float2*)(out + obase + (size_t)(r0i + 8) * NF + col) = make_float2(y0, y1);
        }
    }
}

// ---------------------------------------------------------------------------
extern "C" void kernel_launch(void* const* d_in, const int* in_sizes, int n_in,
                              void* d_out, int out_size) {
    const float* h   = (const float*)d_in[0];
    const int*   adj = (const int*)d_in[1];
    const float* W   = (const float*)d_in[2];
    const float* a   = (const float*)d_in[3];
    float* out = (float*)d_out;

    static_assert(SMEM_FLOATS * 4 < 114 * 1024, "k2 smem too big for 2 CTAs/SM");
    static_assert(K1_SMEM_FLOATS * 4 < 114 * 1024, "k1 smem too big for 2 CTAs/SM");
    cudaFuncSetAttribute(gat_k1, cudaFuncAttributeMaxDynamicSharedMemorySize,
                         K1_SMEM_FLOATS * 4);
    cudaFuncSetAttribute(gat_k2, cudaFuncAttributeMaxDynamicSharedMemorySize,
                         SMEM_FLOATS * 4);

    gat_k1<<<(NB * NN) / 64, 256, K1_SMEM_FLOATS * 4>>>(h, W, a);
    gat_k2<<<NB * (NN / BM), 256, SMEM_FLOATS * 4>>>(adj, out);
}